// round 8
// baseline (speedup 1.0000x reference)
#include <cuda_runtime.h>
#include <cstddef>

// Sparsemax over last dim: rows of D=512 fp32, one warp per row.
// R8: warm-started Michelot (top-3 per lane) + register-slim two-pass body.
//   Pass 1 loads the row, keeps only per-lane top-3 (values die instantly),
//   computes tau exactly (count-stable Michelot from tau0 = max-1).
//   Pass 2 RE-LOADS the row from L1 (2KB/warp x <=64 warps < 228KB L1,
//   reuse distance ~300 cyc) and stores max(0, x - tau).
//   Dropping the 16 resident floats cuts regs ~39 -> ~26, letting 64 warps/SM
//   reside and hide HBM latency.

static constexpr int D   = 512;   // elements per row
static constexpr int VPT = 4;     // float4 loads per thread (4*4*32 = 512)
static constexpr int WPB = 8;     // warps (rows) per block

// Guaranteed re-load (asm volatile defeats CSE against the pass-1 loads),
// cached at all levels so pass 2 hits L1.
__device__ __forceinline__ float4 ld_ca_v4(const float4* p) {
    float4 r;
    asm volatile("ld.global.ca.v4.f32 {%0,%1,%2,%3}, [%4];"
                 : "=f"(r.x), "=f"(r.y), "=f"(r.z), "=f"(r.w)
                 : "l"(p));
    return r;
}

__global__ __launch_bounds__(WPB * 32, 8) void sparsemax_kernel(
    const float* __restrict__ x, float* __restrict__ y, int nrows)
{
    const int gwarp = (blockIdx.x * blockDim.x + threadIdx.x) >> 5;
    if (gwarp >= nrows) return;
    const int lane = threadIdx.x & 31;

    const float4* __restrict__ xr =
        reinterpret_cast<const float4*>(x) + (size_t)gwarp * (D / 4);
    float4* __restrict__ yr =
        reinterpret_cast<float4*>(y) + (size_t)gwarp * (D / 4);

    // Pass 1: coalesced caching loads + branchless per-lane top-3.
    // Values are consumed by the min/max network and die immediately.
    float a1 = -3.402823466e38f, a2 = a1, a3 = a1;
#pragma unroll
    for (int j = 0; j < VPT; j++) {
        const float4 t = xr[lane + 32 * j];
        const float e[4] = {t.x, t.y, t.z, t.w};
#pragma unroll
        for (int k = 0; k < 4; k++) {
            const float n1 = fmaxf(a1, e[k]);
            const float r1 = fminf(a1, e[k]);
            const float n2 = fmaxf(a2, r1);
            const float r2 = fminf(a2, r1);
            a3 = fmaxf(a3, r2);
            a1 = n1; a2 = n2;
        }
    }
    float m = a1;
#pragma unroll
    for (int o = 16; o > 0; o >>= 1)
        m = fmaxf(m, __shfl_xor_sync(0xffffffffu, m, o));

    const float tau0 = m - 1.0f;    // valid lower bound on tau*
    float tau = tau0;

    if (__ballot_sync(0xffffffffu, a3 > tau0) == 0u) {
        // Fast path (~97% of rows): every candidate {x > tau0} is within
        // some lane's {a1, a2}. Iterations only raise tau, so the
        // containment stays valid; count-stable => exact fixed point.
        int prev = -1;
        for (;;) {
            float s = 0.0f;
            int c = 0;
            if (a1 > tau) { s += a1; c++; }
            if (a2 > tau) { s += a2; c++; }
#pragma unroll
            for (int o = 16; o > 0; o >>= 1)
                s += __shfl_xor_sync(0xffffffffu, s, o);
            c = __reduce_add_sync(0xffffffffu, c);   // REDUX.SUM
            if (c == prev) break;
            prev = c;
            tau = (s - 1.0f) / (float)c;
        }
    } else {
        // Rare overflow path (warp-uniform): full Michelot, re-reading the
        // row from L1 each iteration instead of holding 16 registers.
        int prev = -1;
        for (;;) {
            float s = 0.0f;
            int c = 0;
#pragma unroll
            for (int j = 0; j < VPT; j++) {
                const float4 t = ld_ca_v4(&xr[lane + 32 * j]);
                if (t.x > tau) { s += t.x; c++; }
                if (t.y > tau) { s += t.y; c++; }
                if (t.z > tau) { s += t.z; c++; }
                if (t.w > tau) { s += t.w; c++; }
            }
#pragma unroll
            for (int o = 16; o > 0; o >>= 1)
                s += __shfl_xor_sync(0xffffffffu, s, o);
            c = __reduce_add_sync(0xffffffffu, c);
            if (c == prev) break;
            prev = c;
            tau = (s - 1.0f) / (float)c;
        }
    }

    // Pass 2: re-load from L1, streaming vector stores of max(0, x - tau).
#pragma unroll
    for (int j = 0; j < VPT; j++) {
        const float4 t = ld_ca_v4(&xr[lane + 32 * j]);
        float4 o;
        o.x = fmaxf(0.0f, t.x - tau);
        o.y = fmaxf(0.0f, t.y - tau);
        o.z = fmaxf(0.0f, t.z - tau);
        o.w = fmaxf(0.0f, t.w - tau);
        __stcs(&yr[lane + 32 * j], o);
    }
}

extern "C" void kernel_launch(void* const* d_in, const int* in_sizes, int n_in,
                              void* d_out, int out_size)
{
    const float* x = (const float*)d_in[0];
    float* y = (float*)d_out;
    const int nrows = in_sizes[0] / D;              // 32*4096 = 131072
    const int blocks = (nrows + WPB - 1) / WPB;
    sparsemax_kernel<<<blocks, WPB * 32>>>(x, y, nrows);
}